// round 1
// baseline (speedup 1.0000x reference)
#include <cuda_runtime.h>
#include <math.h>

// Tropical (max-plus) matmul:
//   out[b,o] = max_i ( W[o,i] + X[b,i] * factors[o] )
// B=512, OUT=1024, IN=1024, all fp32.
//
// SGEMM-style register-blocked kernel on the fp32 FMA + ALU pipes
// (tensor cores cannot express the max-plus semiring).

#define B_DIM   512
#define OUT_DIM 1024
#define IN_DIM  1024

#define BM 64     // batch tile
#define BN 64     // out tile
#define BK 16     // k tile
#define TM 4      // per-thread batch
#define TN 4      // per-thread out
#define LDS_PAD 68  // 64 + 4: keeps float4 alignment, reduces STS conflicts

__global__ __launch_bounds__(256, 1)
void scaled_maxplus_kernel(const float* __restrict__ X,
                           const float* __restrict__ W,
                           const float* __restrict__ F,
                           float* __restrict__ out)
{
    __shared__ float Xs[2][BK][LDS_PAD];
    __shared__ float Ws[2][BK][LDS_PAD];

    const int tid = threadIdx.x;
    const int tx  = tid & 15;   // n (output) direction, 0..15
    const int ty  = tid >> 4;   // m (batch) direction,  0..15

    const int bm0 = blockIdx.y * BM;
    const int bn0 = blockIdx.x * BN;

    // ---- loader mapping: each thread loads one float4 of X and one of W per stage
    const int lrow = tid >> 2;          // 0..63
    const int lk4  = (tid & 3) << 2;    // 0,4,8,12

    const float4* __restrict__ Xg =
        reinterpret_cast<const float4*>(X + (size_t)(bm0 + lrow) * IN_DIM + lk4);
    const float4* __restrict__ Wg =
        reinterpret_cast<const float4*>(W + (size_t)(bn0 + lrow) * IN_DIM + lk4);
    // stage stride in float4 units: BK/4 = 4

    // ---- per-thread factors (one per output column handled)
    float f[TN];
    #pragma unroll
    for (int j = 0; j < TN; j++)
        f[j] = F[bn0 + tx * TN + j];

    // ---- accumulators
    float acc[TM][TN];
    #pragma unroll
    for (int i = 0; i < TM; i++)
        #pragma unroll
        for (int j = 0; j < TN; j++)
            acc[i][j] = -INFINITY;

    // ---- prologue: load stage 0
    float4 xv = Xg[0];
    float4 wv = Wg[0];
    Xs[0][lk4 + 0][lrow] = xv.x;
    Xs[0][lk4 + 1][lrow] = xv.y;
    Xs[0][lk4 + 2][lrow] = xv.z;
    Xs[0][lk4 + 3][lrow] = xv.w;
    Ws[0][lk4 + 0][lrow] = wv.x;
    Ws[0][lk4 + 1][lrow] = wv.y;
    Ws[0][lk4 + 2][lrow] = wv.z;
    Ws[0][lk4 + 3][lrow] = wv.w;
    __syncthreads();

    const int T = IN_DIM / BK;  // 64
    int cur = 0;

    for (int t = 0; t < T; t++) {
        // prefetch next stage from global (independent of smem)
        if (t + 1 < T) {
            xv = Xg[(t + 1) * (BK / 4)];
            wv = Wg[(t + 1) * (BK / 4)];
        }

        // compute on current stage
        #pragma unroll
        for (int k = 0; k < BK; k++) {
            float4 xr = *reinterpret_cast<const float4*>(&Xs[cur][k][ty * TM]);
            float4 wr = *reinterpret_cast<const float4*>(&Ws[cur][k][tx * TN]);
            float xa[4] = {xr.x, xr.y, xr.z, xr.w};
            float wa[4] = {wr.x, wr.y, wr.z, wr.w};
            #pragma unroll
            for (int i = 0; i < TM; i++)
                #pragma unroll
                for (int j = 0; j < TN; j++)
                    acc[i][j] = fmaxf(acc[i][j], fmaf(xa[i], f[j], wa[j]));
        }

        // stage the prefetched tile into the other buffer.
        // Single sync per iteration is sufficient: the buffer being written
        // was last READ before the previous iteration's sync.
        if (t + 1 < T) {
            const int nxt = cur ^ 1;
            Xs[nxt][lk4 + 0][lrow] = xv.x;
            Xs[nxt][lk4 + 1][lrow] = xv.y;
            Xs[nxt][lk4 + 2][lrow] = xv.z;
            Xs[nxt][lk4 + 3][lrow] = xv.w;
            Ws[nxt][lk4 + 0][lrow] = wv.x;
            Ws[nxt][lk4 + 1][lrow] = wv.y;
            Ws[nxt][lk4 + 2][lrow] = wv.z;
            Ws[nxt][lk4 + 3][lrow] = wv.w;
            __syncthreads();
            cur = nxt;
        }
    }

    // ---- epilogue: 4x4 per thread, float4 stores along OUT
    #pragma unroll
    for (int i = 0; i < TM; i++) {
        float4 v = make_float4(acc[i][0], acc[i][1], acc[i][2], acc[i][3]);
        *reinterpret_cast<float4*>(
            out + (size_t)(bm0 + ty * TM + i) * OUT_DIM + bn0 + tx * TN) = v;
    }
}

extern "C" void kernel_launch(void* const* d_in, const int* in_sizes, int n_in,
                              void* d_out, int out_size)
{
    const float* X = (const float*)d_in[0];   // (512, 1024)
    const float* W = (const float*)d_in[1];   // (1024, 1024)
    const float* F = (const float*)d_in[2];   // (1024, 1)
    float* out = (float*)d_out;               // (512, 1024)

    dim3 grid(OUT_DIM / BN, B_DIM / BM);      // (16, 8) = 128 blocks
    dim3 block(256);
    scaled_maxplus_kernel<<<grid, block>>>(X, W, F, out);
}

// round 2
// speedup vs baseline: 1.0046x; 1.0046x over previous
#include <cuda_runtime.h>
#include <math.h>

// Tropical (max-plus) matmul, split-K version:
//   out[b,o] = max_i ( W[o,i] + X[b,i] * factors[o] )
// B=512, OUT=1024, IN=1024, fp32.
//
// Round 2 design: 64x128 tile, 8x8 register tile, 128 threads, KSPLIT=7
// (448 CTAs ~ 2.95/SM -> 3 CTAs = 12 warps/SM), partials to L2-resident
// scratch, tiny max-reduce kernel.

#define B_DIM   512
#define OUT_DIM 1024
#define IN_DIM  1024

#define BM 64
#define BN 128
#define BK 16
#define TM 8
#define TN 8
#define THREADS 128
#define KSPLIT 7
#define NKT (IN_DIM / BK)     // 64 k-tiles total

#define XPAD 68               // 64 + 4
#define WPAD 132              // 128 + 4

// split-K partials: [KSPLIT][B][OUT]
__device__ float g_scratch[KSPLIT * B_DIM * OUT_DIM];

__global__ __launch_bounds__(THREADS, 3)
void scaled_maxplus_partial(const float* __restrict__ X,
                            const float* __restrict__ W,
                            const float* __restrict__ F)
{
    __shared__ float Xs[2][BK][XPAD];
    __shared__ float Ws[2][BK][WPAD];

    const int tid = threadIdx.x;
    const int tx  = tid & 15;   // n direction, 0..15  (8 cols each)
    const int ty  = tid >> 4;   // m direction, 0..7   (8 rows each)

    const int bm0 = blockIdx.y * BM;
    const int bn0 = blockIdx.x * BN;
    const int z   = blockIdx.z;

    // k-tile range for this split (uneven 9/10 split over 64 tiles)
    const int t0 = (z * NKT) / KSPLIT;
    const int t1 = ((z + 1) * NKT) / KSPLIT;

    // ---- loader mapping (float4 granularity)
    // X stage: 16x64 = 256 float4; 2 per thread (rows r, r+32)
    // W stage: 16x128 = 512 float4; 4 per thread (rows r, r+32, r+64, r+96)
    const int lrow = tid >> 2;          // 0..31
    const int lk4  = (tid & 3) << 2;    // 0,4,8,12

    const float4* __restrict__ Xg0 =
        reinterpret_cast<const float4*>(X + (size_t)(bm0 + lrow) * IN_DIM + lk4);
    const float4* __restrict__ Xg1 =
        reinterpret_cast<const float4*>(X + (size_t)(bm0 + lrow + 32) * IN_DIM + lk4);
    const float4* __restrict__ Wg0 =
        reinterpret_cast<const float4*>(W + (size_t)(bn0 + lrow) * IN_DIM + lk4);
    const float4* __restrict__ Wg1 =
        reinterpret_cast<const float4*>(W + (size_t)(bn0 + lrow + 32) * IN_DIM + lk4);
    const float4* __restrict__ Wg2 =
        reinterpret_cast<const float4*>(W + (size_t)(bn0 + lrow + 64) * IN_DIM + lk4);
    const float4* __restrict__ Wg3 =
        reinterpret_cast<const float4*>(W + (size_t)(bn0 + lrow + 96) * IN_DIM + lk4);
    // per k-tile stride in float4: BK/4 = 4

    // ---- per-thread factors
    float f[TN];
    #pragma unroll
    for (int j = 0; j < TN; j++)
        f[j] = F[bn0 + tx * TN + j];

    float acc[TM][TN];
    #pragma unroll
    for (int i = 0; i < TM; i++)
        #pragma unroll
        for (int j = 0; j < TN; j++)
            acc[i][j] = -INFINITY;

    // ---- prologue: load k-tile t0 into stage 0
    {
        const int off = t0 * (BK / 4);
        float4 xa = Xg0[off], xb = Xg1[off];
        float4 wa = Wg0[off], wb = Wg1[off], wc = Wg2[off], wd = Wg3[off];
        Xs[0][lk4+0][lrow]    = xa.x; Xs[0][lk4+1][lrow]    = xa.y;
        Xs[0][lk4+2][lrow]    = xa.z; Xs[0][lk4+3][lrow]    = xa.w;
        Xs[0][lk4+0][lrow+32] = xb.x; Xs[0][lk4+1][lrow+32] = xb.y;
        Xs[0][lk4+2][lrow+32] = xb.z; Xs[0][lk4+3][lrow+32] = xb.w;
        Ws[0][lk4+0][lrow]    = wa.x; Ws[0][lk4+1][lrow]    = wa.y;
        Ws[0][lk4+2][lrow]    = wa.z; Ws[0][lk4+3][lrow]    = wa.w;
        Ws[0][lk4+0][lrow+32] = wb.x; Ws[0][lk4+1][lrow+32] = wb.y;
        Ws[0][lk4+2][lrow+32] = wb.z; Ws[0][lk4+3][lrow+32] = wb.w;
        Ws[0][lk4+0][lrow+64] = wc.x; Ws[0][lk4+1][lrow+64] = wc.y;
        Ws[0][lk4+2][lrow+64] = wc.z; Ws[0][lk4+3][lrow+64] = wc.w;
        Ws[0][lk4+0][lrow+96] = wd.x; Ws[0][lk4+1][lrow+96] = wd.y;
        Ws[0][lk4+2][lrow+96] = wd.z; Ws[0][lk4+3][lrow+96] = wd.w;
    }
    __syncthreads();

    int cur = 0;
    for (int t = t0; t < t1; t++) {
        // prefetch next tile from global (independent of smem)
        float4 xa, xb, wa, wb, wc, wd;
        const bool more = (t + 1 < t1);
        if (more) {
            const int off = (t + 1) * (BK / 4);
            xa = Xg0[off]; xb = Xg1[off];
            wa = Wg0[off]; wb = Wg1[off]; wc = Wg2[off]; wd = Wg3[off];
        }

        // compute on current stage
        #pragma unroll
        for (int k = 0; k < BK; k++) {
            float4 x0 = *reinterpret_cast<const float4*>(&Xs[cur][k][ty * TM]);
            float4 x1 = *reinterpret_cast<const float4*>(&Xs[cur][k][ty * TM + 4]);
            float4 w0 = *reinterpret_cast<const float4*>(&Ws[cur][k][tx * TN]);
            float4 w1 = *reinterpret_cast<const float4*>(&Ws[cur][k][tx * TN + 4]);
            float xr[8] = {x0.x, x0.y, x0.z, x0.w, x1.x, x1.y, x1.z, x1.w};
            float wr[8] = {w0.x, w0.y, w0.z, w0.w, w1.x, w1.y, w1.z, w1.w};
            #pragma unroll
            for (int i = 0; i < TM; i++)
                #pragma unroll
                for (int j = 0; j < TN; j++)
                    acc[i][j] = fmaxf(acc[i][j], fmaf(xr[i], f[j], wr[j]));
        }

        if (more) {
            const int nxt = cur ^ 1;
            Xs[nxt][lk4+0][lrow]    = xa.x; Xs[nxt][lk4+1][lrow]    = xa.y;
            Xs[nxt][lk4+2][lrow]    = xa.z; Xs[nxt][lk4+3][lrow]    = xa.w;
            Xs[nxt][lk4+0][lrow+32] = xb.x; Xs[nxt][lk4+1][lrow+32] = xb.y;
            Xs[nxt][lk4+2][lrow+32] = xb.z; Xs[nxt][lk4+3][lrow+32] = xb.w;
            Ws[nxt][lk4+0][lrow]    = wa.x; Ws[nxt][lk4+1][lrow]    = wa.y;
            Ws[nxt][lk4+2][lrow]    = wa.z; Ws[nxt][lk4+3][lrow]    = wa.w;
            Ws[nxt][lk4+0][lrow+32] = wb.x; Ws[nxt][lk4+1][lrow+32] = wb.y;
            Ws[nxt][lk4+2][lrow+32] = wb.z; Ws[nxt][lk4+3][lrow+32] = wb.w;
            Ws[nxt][lk4+0][lrow+64] = wc.x; Ws[nxt][lk4+1][lrow+64] = wc.y;
            Ws[nxt][lk4+2][lrow+64] = wc.z; Ws[nxt][lk4+3][lrow+64] = wc.w;
            Ws[nxt][lk4+0][lrow+96] = wd.x; Ws[nxt][lk4+1][lrow+96] = wd.y;
            Ws[nxt][lk4+2][lrow+96] = wd.z; Ws[nxt][lk4+3][lrow+96] = wd.w;
            __syncthreads();
            cur = nxt;
        }
    }

    // ---- epilogue: write 8x8 partial tile to scratch[z]
    float* dst_base = g_scratch + (size_t)z * B_DIM * OUT_DIM;
    #pragma unroll
    for (int i = 0; i < TM; i++) {
        float* dst = dst_base + (size_t)(bm0 + ty * TM + i) * OUT_DIM + bn0 + tx * TN;
        *reinterpret_cast<float4*>(dst) =
            make_float4(acc[i][0], acc[i][1], acc[i][2], acc[i][3]);
        *reinterpret_cast<float4*>(dst + 4) =
            make_float4(acc[i][4], acc[i][5], acc[i][6], acc[i][7]);
    }
}

__global__ __launch_bounds__(256)
void maxreduce_splits(float* __restrict__ out)
{
    const int idx4 = blockIdx.x * blockDim.x + threadIdx.x;  // float4 index
    const int n4 = B_DIM * OUT_DIM / 4;
    if (idx4 >= n4) return;

    const float4* s = reinterpret_cast<const float4*>(g_scratch);
    float4 m = s[idx4];
    #pragma unroll
    for (int z = 1; z < KSPLIT; z++) {
        float4 v = s[(size_t)z * n4 + idx4];
        m.x = fmaxf(m.x, v.x);
        m.y = fmaxf(m.y, v.y);
        m.z = fmaxf(m.z, v.z);
        m.w = fmaxf(m.w, v.w);
    }
    reinterpret_cast<float4*>(out)[idx4] = m;
}

extern "C" void kernel_launch(void* const* d_in, const int* in_sizes, int n_in,
                              void* d_out, int out_size)
{
    const float* X = (const float*)d_in[0];   // (512, 1024)
    const float* W = (const float*)d_in[1];   // (1024, 1024)
    const float* F = (const float*)d_in[2];   // (1024, 1)
    float* out = (float*)d_out;               // (512, 1024)

    dim3 grid(OUT_DIM / BN, B_DIM / BM, KSPLIT);   // (8, 8, 7) = 448 CTAs
    scaled_maxplus_partial<<<grid, THREADS>>>(X, W, F);

    const int n4 = B_DIM * OUT_DIM / 4;            // 131072
    maxreduce_splits<<<(n4 + 255) / 256, 256>>>(out);
}